// round 4
// baseline (speedup 1.0000x reference)
#include <cuda_runtime.h>
#include <cstdint>

#define BATCH 1024
#define TT 13
#define YY 188
#define HH 512
#define GG 1536
#define DS 13
#define KPAD 192
#define NTH 256
#define BKc 32
#define BNc 192
#define SEPIL 196
#define RSTR 144                 // 36 floats * 4B padded smem row stride
#define BSTR (BNc * RSTR)        // 27648

// ---------------- scratch ----------------
__device__ float g_xg0[(size_t)TT * BATCH * GG];   // ring: xg0 + b_ih0 (permuted cols)
__device__ float g_gh1[(size_t)BATCH * GG];
__device__ float g_h0[2][(size_t)BATCH * HH];
__device__ float g_h1[2][(size_t)BATCH * HH];
__device__ float g_xlast[(size_t)BATCH * YY];      // raw (exact outputs / residual)
__device__ float g_xlastr[(size_t)BATCH * YY];     // tf32-rounded (GEMM A)
__device__ float g_xp[(size_t)BATCH * TT * YY];    // tf32-rounded x
__device__ float g_Whh0p[(size_t)GG * HH];
__device__ float g_Wih1p[(size_t)GG * HH];
__device__ float g_Whh1p[(size_t)GG * HH];
__device__ float g_Wih0p[(size_t)GG * KPAD];
__device__ float g_Woutp[(size_t)KPAD * HH];
__device__ float g_bih0p[GG], g_bhh0p[GG], g_bih1p[GG], g_bhh1p[GG];

// ---------------- helpers ----------------
__device__ __forceinline__ float tf32r(float x) {
    uint32_t u; asm("cvt.rna.tf32.f32 %0, %1;" : "=r"(u) : "f"(x));
    return __uint_as_float(u);
}
__device__ __forceinline__ void cp16(uint32_t d, const void* s) {
    asm volatile("cp.async.cg.shared.global [%0], [%1], 16;\n" :: "r"(d), "l"(s));
}
__device__ __forceinline__ void cpc()  { asm volatile("cp.async.commit_group;\n"); }
__device__ __forceinline__ void cpw1() { asm volatile("cp.async.wait_group 1;\n"); }
__device__ __forceinline__ float lds32(uint32_t a) {
    float v; asm volatile("ld.shared.f32 %0, [%1];" : "=f"(v) : "r"(a)); return v;
}
__device__ __forceinline__ float sigm(float x)   { return 1.f / (1.f + __expf(-x)); }
__device__ __forceinline__ float tanhf_(float x) { return 2.f * sigm(2.f * x) - 1.f; }

__device__ __forceinline__ void mma8(float* d, const float* a, float b0f, float b1f) {
    uint32_t b0 = __float_as_uint(b0f), b1 = __float_as_uint(b1f);
    asm volatile(
        "mma.sync.aligned.m16n8k8.row.col.f32.tf32.tf32.f32 "
        "{%0,%1,%2,%3},{%4,%5,%6,%7},{%8,%9},{%0,%1,%2,%3};\n"
        : "+f"(d[0]), "+f"(d[1]), "+f"(d[2]), "+f"(d[3])
        : "r"(__float_as_uint(a[0])), "r"(__float_as_uint(a[1])),
          "r"(__float_as_uint(a[2])), "r"(__float_as_uint(a[3])),
          "r"(b0), "r"(b1));
}

// modes
#define M_GATE0 0
#define M_GATE1 1
#define M_STORE 2
#define M_XGALL 4
#define M_OUT   5

// ---------------- GEMM core ----------------
template<int BM, int MODE, int NK, bool ZG, bool RELU_A>
__device__ __forceinline__ void gcore(
    const float* __restrict__ A, int lda, int KA,
    const float* __restrict__ Bw, int ldb,
    const float* __restrict__ biasg,
    const float* __restrict__ gh, const float* __restrict__ bhh,
    const float* __restrict__ hsrc, float* __restrict__ hdst,
    float* __restrict__ C,
    float* __restrict__ dout, int dstep)
{
    constexpr int IC = BM / 32;          // mma row-steps per warp (warpM count = 2)
    constexpr int ASTR = BM * RSTR;

    extern __shared__ float sm[];
    const uint32_t sAb = (uint32_t)__cvta_generic_to_shared(sm);
    const uint32_t sBb = sAb + 3 * ASTR;

    const int tid = threadIdx.x, lane = tid & 31, warp = tid >> 5;
    const int warpM = warp >> 2, warpN = warp & 3;   // 2 x 4
    const int lane4 = lane >> 2, lq = lane & 3;
    const int m0 = blockIdx.y * BM, n0 = blockIdx.x * BNc;

    float acc[IC][6][4];
#pragma unroll
    for (int i = 0; i < IC; i++)
#pragma unroll
        for (int j = 0; j < 6; j++)
#pragma unroll
            for (int q = 0; q < 4; q++) acc[i][j][q] = 0.f;

    auto loadStage = [&](int st, int k0) {
#pragma unroll
        for (int v = tid; v < BM * 8; v += NTH) {
            int r = v >> 3, vc = v & 7, kk = k0 + vc * 4;
            const float* src = A + (size_t)(m0 + r) * lda + (kk < KA ? kk : 0);
            cp16(sAb + st * ASTR + r * RSTR + vc * 16, src);
        }
#pragma unroll
        for (int v = tid; v < BNc * 8; v += NTH) {
            int r = v >> 3, vc = v & 7, kk = k0 + vc * 4;
            cp16(sBb + st * BSTR + r * RSTR + vc * 16,
                 Bw + (size_t)(n0 + r) * ldb + kk);
        }
    };

    loadStage(0, 0);   cpc();
    loadStage(1, BKc); cpc();

    const uint32_t aB0 = sAb + (uint32_t)(warpM * (BM / 2) + lane4) * RSTR + lq * 4;
    const uint32_t bB0 = sBb + (uint32_t)(warpN * 48 + lane4) * RSTR + lq * 4;

    for (int kt = 0; kt < NK; kt++) {
        cpw1();
        __syncthreads();
        if (kt + 2 < NK) loadStage((kt + 2) % 3, (kt + 2) * BKc);
        cpc();

        const int st = kt % 3;
        const uint32_t aS = aB0 + st * ASTR;
        const uint32_t bS = bB0 + st * BSTR;
#pragma unroll
        for (int ks = 0; ks < 4; ks++) {
            float af[IC][4];
#pragma unroll
            for (int i = 0; i < IC; i++) {
                uint32_t base = aS + i * (16 * RSTR) + ks * 32;
                af[i][0] = lds32(base);
                af[i][1] = lds32(base + 8 * RSTR);
                af[i][2] = lds32(base + 16);
                af[i][3] = lds32(base + 8 * RSTR + 16);
                if (RELU_A) {
#pragma unroll
                    for (int q = 0; q < 4; q++) af[i][q] = fmaxf(af[i][q], 0.f);
                }
            }
#pragma unroll
            for (int j = 0; j < 6; j++) {
                float b0 = lds32(bS + j * (8 * RSTR) + ks * 32);
                float b1 = lds32(bS + j * (8 * RSTR) + ks * 32 + 16);
#pragma unroll
                for (int i = 0; i < IC; i++) mma8(acc[i][j], af[i], b0, b1);
            }
        }
    }
    __syncthreads();

    // ---------------- epilogues ----------------
    if (MODE == M_STORE || MODE == M_XGALL) {
#pragma unroll
        for (int i = 0; i < IC; i++) {
            int rr = m0 + warpM * (BM / 2) + i * 16 + lane4;
#pragma unroll
            for (int j = 0; j < 6; j++) {
                int cc = n0 + warpN * 48 + j * 8 + lq * 2;
#pragma unroll
                for (int q = 0; q < 4; q++) {
                    int r2 = rr + (q >> 1) * 8, c2 = cc + (q & 1);
                    float v = acc[i][j][q] + biasg[c2];
                    if (MODE == M_STORE) {
                        C[(size_t)r2 * GG + c2] = v;
                    } else {
                        int b = r2 / TT, t = r2 % TT;
                        C[((size_t)t * BATCH + b) * GG + c2] = v;
                    }
                }
            }
        }
    } else if (MODE == M_OUT) {
#pragma unroll
        for (int i = 0; i < IC; i++) {
            int rr = m0 + warpM * (BM / 2) + i * 16 + lane4;
#pragma unroll
            for (int j = 0; j < 6; j++) {
                int cc = n0 + warpN * 48 + j * 8 + lq * 2;
#pragma unroll
                for (int q = 0; q < 4; q++) {
                    int r2 = rr + (q >> 1) * 8, c2 = cc + (q & 1);
                    if (c2 < YY) {
                        float v = acc[i][j][q] + biasg[c2] + g_xlast[(size_t)r2 * YY + c2];
                        dout[((size_t)r2 * DS + dstep) * YY + c2] = v;
                        g_xlast[(size_t)r2 * YY + c2] = v;
                        g_xlastr[(size_t)r2 * YY + c2] = tf32r(v);
                    }
                }
            }
        }
    } else {  // M_GATE0 / M_GATE1
#pragma unroll
        for (int i = 0; i < IC; i++) {
            int rl = warpM * (BM / 2) + i * 16 + lane4;
#pragma unroll
            for (int j = 0; j < 6; j++) {
                int cl = warpN * 48 + j * 8 + lq * 2;
                *(float2*)&sm[rl * SEPIL + cl]       = make_float2(acc[i][j][0], acc[i][j][1]);
                *(float2*)&sm[(rl + 8) * SEPIL + cl] = make_float2(acc[i][j][2], acc[i][j][3]);
            }
        }
        __syncthreads();
        const int jbase = n0 / 3;
        for (int idx = tid; idx < BM * 64; idx += NTH) {
            int bl = idx >> 6, jj = idx & 63;
            int b = m0 + bl;
            int cg = n0 + 3 * jj;
            float ar = sm[bl * SEPIL + 3 * jj + 0];
            float az = sm[bl * SEPIL + 3 * jj + 1];
            float an = sm[bl * SEPIL + 3 * jj + 2];
            float xr, xz, xn, gr, gz, gn, hp;
            if (MODE == M_GATE0) {
                const float* xg = gh + (size_t)b * GG;
                xr = xg[cg]; xz = xg[cg + 1]; xn = xg[cg + 2];
                gr = ar + bhh[cg]; gz = az + bhh[cg + 1]; gn = an + bhh[cg + 2];
                hp = hsrc[(size_t)b * HH + jbase + jj];
            } else {
                xr = ar + biasg[cg]; xz = az + biasg[cg + 1]; xn = an + biasg[cg + 2];
                if (ZG) {
                    gr = bhh[cg]; gz = bhh[cg + 1]; gn = bhh[cg + 2]; hp = 0.f;
                } else {
                    const float* g = gh + (size_t)b * GG;
                    gr = g[cg]; gz = g[cg + 1]; gn = g[cg + 2];
                    hp = hsrc[(size_t)b * HH + jbase + jj];
                }
            }
            float r = sigm(xr + gr), z = sigm(xz + gz);
            float nn_ = tanhf_(xn + r * gn);
            hdst[(size_t)b * HH + jbase + jj] = tf32r((1.f - z) * nn_ + z * hp);
        }
    }
}

// ---------------- kernels ----------------
#define SM128 (3 * (128 * RSTR + BSTR))   // 138240
#define SM64  (3 * (64 * RSTR + BSTR))    // 110592

__global__ void __launch_bounds__(NTH, 1) k_rec(int par, int slot) {
    if (blockIdx.z == 0)
        gcore<128, M_GATE0, 16, false, false>(g_h0[par ^ 1], HH, HH, g_Whh0p, HH,
            nullptr, g_xg0 + (size_t)slot * BATCH * GG, g_bhh0p,
            g_h0[par ^ 1], g_h0[par], nullptr, nullptr, 0);
    else
        gcore<128, M_STORE, 16, false, false>(g_h1[par ^ 1], HH, HH, g_Whh1p, HH,
            g_bhh1p, nullptr, nullptr, nullptr, nullptr, g_gh1, nullptr, 0);
}

template<bool ZG>
__global__ void __launch_bounds__(NTH, 1) k_xg1(int par) {
    gcore<64, M_GATE1, 16, ZG, false>(g_h0[par], HH, HH, g_Wih1p, HH,
        g_bih1p, g_gh1, g_bhh1p,
        g_h1[par ^ 1], g_h1[par], nullptr, nullptr, 0);
}

__global__ void __launch_bounds__(NTH, 1) k_xg0_all() {
    gcore<128, M_XGALL, 6, false, false>(g_xp, YY, YY, g_Wih0p, KPAD,
        g_bih0p, nullptr, nullptr, nullptr, nullptr, g_xg0, nullptr, 0);
}

__global__ void __launch_bounds__(NTH, 1) k_xg0_new(int slot) {
    gcore<64, M_STORE, 6, false, false>(g_xlastr, YY, YY, g_Wih0p, KPAD,
        g_bih0p, nullptr, nullptr, nullptr, nullptr,
        g_xg0 + (size_t)slot * BATCH * GG, nullptr, 0);
}

__global__ void __launch_bounds__(NTH, 1) k_out(float* __restrict__ dout, int dstep,
                                                const float* __restrict__ bout) {
    gcore<64, M_OUT, 16, false, true>(g_h1[0], HH, HH, g_Woutp, HH,
        bout, nullptr, nullptr, nullptr, nullptr, nullptr, dout, dstep);
}

__global__ void k_gate0_init(int slot) {
    int idx = blockIdx.x * blockDim.x + threadIdx.x;
    if (idx >= BATCH * HH) return;
    int b = idx >> 9, j = idx & 511;
    const float* xg = g_xg0 + (size_t)slot * BATCH * GG + (size_t)b * GG;
    int c = 3 * j;
    float r = sigm(xg[c] + g_bhh0p[c]);
    float z = sigm(xg[c + 1] + g_bhh0p[c + 1]);
    float n = tanhf_(xg[c + 2] + r * g_bhh0p[c + 2]);
    g_h0[0][idx] = tf32r((1.f - z) * n);
}

__global__ void k_init(const float* __restrict__ x) {
    int idx = blockIdx.x * blockDim.x + threadIdx.x;
    if (idx < BATCH * TT * YY) g_xp[idx] = tf32r(x[idx]);
    if (idx < BATCH * YY) {
        int b = idx / YY, y = idx % YY;
        float v = x[((size_t)b * TT + (TT - 1)) * YY + y];
        g_xlast[idx] = v;
        g_xlastr[idx] = tf32r(v);
    }
}

__global__ void k_prep(const float* __restrict__ Wih0, const float* __restrict__ Whh0,
                       const float* __restrict__ bih0, const float* __restrict__ bhh0,
                       const float* __restrict__ Wih1, const float* __restrict__ Whh1,
                       const float* __restrict__ bih1, const float* __restrict__ bhh1,
                       const float* __restrict__ Wout) {
    int i = blockIdx.x * blockDim.x + threadIdx.x;
    if (i < GG * HH) {
        int c = i / HH, k = i % HH;
        int pr = (c % 3) * HH + c / 3;
        g_Whh0p[i] = tf32r(Whh0[(size_t)pr * HH + k]);
        g_Wih1p[i] = tf32r(Wih1[(size_t)pr * HH + k]);
        g_Whh1p[i] = tf32r(Whh1[(size_t)pr * HH + k]);
    }
    if (i < GG * KPAD) {
        int c = i / KPAD, k = i % KPAD;
        int pr = (c % 3) * HH + c / 3;
        g_Wih0p[i] = (k < YY) ? tf32r(Wih0[(size_t)pr * YY + k]) : 0.f;
    }
    if (i < KPAD * HH) {
        int r = i / HH, k = i % HH;
        g_Woutp[i] = (r < YY) ? tf32r(Wout[(size_t)r * HH + k]) : 0.f;
    }
    if (i < GG) {
        int pr = (i % 3) * HH + i / 3;
        g_bih0p[i] = bih0[pr];
        g_bhh0p[i] = bhh0[pr];
        g_bih1p[i] = bih1[pr];
        g_bhh1p[i] = bhh1[pr];
    }
}

// ---------------- host ----------------
extern "C" void kernel_launch(void* const* d_in, const int* in_sizes, int n_in,
                              void* d_out, int out_size) {
    (void)in_sizes; (void)n_in; (void)out_size;
    const float* x    = (const float*)d_in[0];
    const float* Wih0 = (const float*)d_in[1];
    const float* Whh0 = (const float*)d_in[2];
    const float* bih0 = (const float*)d_in[3];
    const float* bhh0 = (const float*)d_in[4];
    const float* Wih1 = (const float*)d_in[5];
    const float* Whh1 = (const float*)d_in[6];
    const float* bih1 = (const float*)d_in[7];
    const float* bhh1 = (const float*)d_in[8];
    const float* Wout = (const float*)d_in[9];
    const float* bout = (const float*)d_in[10];
    float* dout = (float*)d_out;

    cudaFuncSetAttribute(k_rec,        cudaFuncAttributeMaxDynamicSharedMemorySize, SM128);
    cudaFuncSetAttribute(k_xg0_all,    cudaFuncAttributeMaxDynamicSharedMemorySize, SM128);
    cudaFuncSetAttribute(k_xg1<true>,  cudaFuncAttributeMaxDynamicSharedMemorySize, SM64);
    cudaFuncSetAttribute(k_xg1<false>, cudaFuncAttributeMaxDynamicSharedMemorySize, SM64);
    cudaFuncSetAttribute(k_xg0_new,    cudaFuncAttributeMaxDynamicSharedMemorySize, SM64);
    cudaFuncSetAttribute(k_out,        cudaFuncAttributeMaxDynamicSharedMemorySize, SM64);

    k_prep<<<(GG * HH + 255) / 256, 256>>>(Wih0, Whh0, bih0, bhh0,
                                           Wih1, Whh1, bih1, bhh1, Wout);
    k_init<<<(BATCH * TT * YY + 255) / 256, 256>>>(x);
    k_xg0_all<<<dim3(GG / BNc, BATCH * TT / 128), NTH, SM128>>>();

    for (int d = 0; d < DS; d++) {
        k_gate0_init<<<(BATCH * HH + 255) / 256, 256>>>(d % TT);
        k_xg1<true><<<dim3(GG / BNc, BATCH / 64), NTH, SM64>>>(0);
        for (int t = 1; t < TT; t++) {
            k_rec<<<dim3(GG / BNc, BATCH / 128, 2), NTH, SM128>>>(t & 1, (d + t) % TT);
            k_xg1<false><<<dim3(GG / BNc, BATCH / 64), NTH, SM64>>>(t & 1);
        }
        k_out<<<dim3(1, BATCH / 64), NTH, SM64>>>(dout, d, bout);
        if (d + 1 < DS) k_xg0_new<<<dim3(GG / BNc, BATCH / 64), NTH, SM64>>>(d % TT);
    }
}

// round 5
// speedup vs baseline: 1.4341x; 1.4341x over previous
#include <cuda_runtime.h>
#include <cuda_fp16.h>
#include <cstdint>

#define BATCH 1024
#define TT 13
#define YY 188
#define HH 512
#define GG 1536
#define DS 13
#define KPAD 192
#define NTH 256
#define SEPIL 196

// ---------------- scratch ----------------
__device__ float  g_xg0[(size_t)TT * BATCH * GG];   // ring: xg0 + b_ih0 (permuted cols)
__device__ float  g_gh1[(size_t)BATCH * GG];
__device__ float  g_h0[2][(size_t)BATCH * HH];
__device__ __half g_h0f[2][(size_t)BATCH * HH];
__device__ float  g_h1[2][(size_t)BATCH * HH];
__device__ __half g_h1f[2][(size_t)BATCH * HH];
__device__ float  g_xlast[(size_t)BATCH * YY];      // exact outputs / residual
__device__ __half g_xlastf[(size_t)BATCH * KPAD];   // fp16, zero-padded 188..191
__device__ __half g_xpf[(size_t)BATCH * TT * KPAD]; // fp16 x, zero-padded
__device__ __half g_Whh0h[(size_t)GG * HH];
__device__ __half g_Wih1h[(size_t)GG * HH];
__device__ __half g_Whh1h[(size_t)GG * HH];
__device__ __half g_Wih0h[(size_t)GG * KPAD];
__device__ __half g_Wouth[(size_t)KPAD * HH];       // 192 rows (188 real) x 512
__device__ float g_bih0p[GG], g_bhh0p[GG], g_bih1p[GG], g_bhh1p[GG];

// ---------------- helpers ----------------
__device__ __forceinline__ void cp16(uint32_t d, const void* s) {
    asm volatile("cp.async.cg.shared.global [%0], [%1], 16;\n" :: "r"(d), "l"(s));
}
__device__ __forceinline__ void cpc()  { asm volatile("cp.async.commit_group;\n"); }
__device__ __forceinline__ void cpw1() { asm volatile("cp.async.wait_group 1;\n"); }
__device__ __forceinline__ float sigm(float x)   { return 1.f / (1.f + __expf(-x)); }
__device__ __forceinline__ float tanhf_(float x) { return 2.f * sigm(2.f * x) - 1.f; }

__device__ __forceinline__ void ldm4(uint32_t* r, uint32_t a) {
    asm volatile("ldmatrix.sync.aligned.m8n8.x4.shared.b16 {%0,%1,%2,%3}, [%4];"
        : "=r"(r[0]), "=r"(r[1]), "=r"(r[2]), "=r"(r[3]) : "r"(a));
}
__device__ __forceinline__ uint32_t relu2(uint32_t v) {
    uint32_t r; asm("max.f16x2 %0, %1, %2;" : "=r"(r) : "r"(v), "r"(0u)); return r;
}
__device__ __forceinline__ void mma16(float* d, const uint32_t* a, uint32_t b0, uint32_t b1) {
    asm volatile("mma.sync.aligned.m16n8k16.row.col.f32.f16.f16.f32 "
        "{%0,%1,%2,%3},{%4,%5,%6,%7},{%8,%9},{%0,%1,%2,%3};"
        : "+f"(d[0]), "+f"(d[1]), "+f"(d[2]), "+f"(d[3])
        : "r"(a[0]), "r"(a[1]), "r"(a[2]), "r"(a[3]), "r"(b0), "r"(b1));
}

// modes
#define M_GATE0 0
#define M_GATE1 1
#define M_STORE 2
#define M_XGALL 4
#define M_OUT   5

// ---------------- GEMM core (fp16 HMMA, BK=64 halves = 128B rows) ----------------
template<int BM, int MODE, int NK, bool ZG, bool RELU_A>
__device__ __forceinline__ void gcore(
    const __half* __restrict__ A, int lda,
    const __half* __restrict__ Bw, int ldb,
    const float* __restrict__ biasg,
    const float* __restrict__ gh, const float* __restrict__ bhh,
    const float* __restrict__ hsrc, float* __restrict__ hdst, __half* __restrict__ hdstf,
    float* __restrict__ C, float* __restrict__ dout, int dstep)
{
    constexpr int IC = BM / 32;          // m16 blocks per warp (warp covers BM/2 rows)
    constexpr int ASTR = BM * 128;       // bytes per A stage
    constexpr int BSTRb = 192 * 128;     // bytes per B stage

    extern __shared__ float sm[];
    const uint32_t sAb = (uint32_t)__cvta_generic_to_shared(sm);
    const uint32_t sBb = sAb + 3 * ASTR;

    const int tid = threadIdx.x, lane = tid & 31, warp = tid >> 5;
    const int warpM = warp >> 2, warpN = warp & 3;   // 2 x 4 warp grid
    const int lane4 = lane >> 2, lq = lane & 3;
    const int m0 = blockIdx.y * BM, n0 = blockIdx.x * 192;

    float acc[IC][6][4];
#pragma unroll
    for (int i = 0; i < IC; i++)
#pragma unroll
        for (int j = 0; j < 6; j++)
#pragma unroll
            for (int q = 0; q < 4; q++) acc[i][j][q] = 0.f;

    auto loadStage = [&](int st, int k0) {   // k0 in halves
#pragma unroll
        for (int v = tid; v < BM * 8; v += NTH) {
            int r = v >> 3, vc = v & 7;
            cp16(sAb + st * ASTR + r * 128 + ((vc ^ (r & 7)) << 4),
                 A + (size_t)(m0 + r) * lda + k0 + vc * 8);
        }
#pragma unroll
        for (int v = tid; v < 192 * 8; v += NTH) {
            int r = v >> 3, vc = v & 7;
            cp16(sBb + st * BSTRb + r * 128 + ((vc ^ (r & 7)) << 4),
                 Bw + (size_t)(n0 + r) * ldb + k0 + vc * 8);
        }
    };

    loadStage(0, 0);  cpc();
    loadStage(1, 64); cpc();

    // ldmatrix per-thread base addresses
    const int subrow = lane & 7;
    uint32_t aBase[IC]; int r7A[IC];
#pragma unroll
    for (int i = 0; i < IC; i++) {
        int row = warpM * (BM / 2) + i * 16 + subrow + ((lane >> 3) & 1) * 8;
        aBase[i] = sAb + row * 128; r7A[i] = row & 7;
    }
    uint32_t bBase[3]; int r7B[3];
#pragma unroll
    for (int jj = 0; jj < 3; jj++) {
        int row = warpN * 48 + jj * 16 + subrow + (lane >> 4) * 8;
        bBase[jj] = sBb + row * 128; r7B[jj] = row & 7;
    }
    const int kvA = lane >> 4;          // 0/1 : second 16B of k16
    const int kvB = (lane >> 3) & 1;

    for (int kt = 0; kt < NK; kt++) {
        cpw1();
        __syncthreads();
        if (kt + 2 < NK) loadStage((kt + 2) % 3, (kt + 2) * 64);
        cpc();

        const int st = kt % 3;
#pragma unroll
        for (int ks = 0; ks < 4; ks++) {
            uint32_t a[IC][4];
#pragma unroll
            for (int i = 0; i < IC; i++) {
                ldm4(a[i], aBase[i] + st * ASTR + (((2 * ks + kvA) ^ r7A[i]) << 4));
                if (RELU_A) {
#pragma unroll
                    for (int q = 0; q < 4; q++) a[i][q] = relu2(a[i][q]);
                }
            }
            uint32_t bf[3][4];
#pragma unroll
            for (int jj = 0; jj < 3; jj++)
                ldm4(bf[jj], bBase[jj] + st * BSTRb + (((2 * ks + kvB) ^ r7B[jj]) << 4));
#pragma unroll
            for (int j = 0; j < 6; j++)
#pragma unroll
                for (int i = 0; i < IC; i++)
                    mma16(acc[i][j], a[i], bf[j >> 1][(j & 1) * 2], bf[j >> 1][(j & 1) * 2 + 1]);
        }
    }
    __syncthreads();

    // ---------------- epilogues ----------------
    if (MODE == M_STORE || MODE == M_XGALL) {
#pragma unroll
        for (int i = 0; i < IC; i++) {
            int rr = m0 + warpM * (BM / 2) + i * 16 + lane4;
#pragma unroll
            for (int j = 0; j < 6; j++) {
                int cc = n0 + warpN * 48 + j * 8 + lq * 2;
#pragma unroll
                for (int q = 0; q < 4; q++) {
                    int r2 = rr + (q >> 1) * 8, c2 = cc + (q & 1);
                    float v = acc[i][j][q] + biasg[c2];
                    if (MODE == M_STORE) {
                        C[(size_t)r2 * GG + c2] = v;
                    } else {
                        int b = r2 / TT, t = r2 % TT;
                        C[((size_t)t * BATCH + b) * GG + c2] = v;
                    }
                }
            }
        }
    } else if (MODE == M_OUT) {
#pragma unroll
        for (int i = 0; i < IC; i++) {
            int rr = m0 + warpM * (BM / 2) + i * 16 + lane4;
#pragma unroll
            for (int j = 0; j < 6; j++) {
                int cc = n0 + warpN * 48 + j * 8 + lq * 2;
#pragma unroll
                for (int q = 0; q < 4; q++) {
                    int r2 = rr + (q >> 1) * 8, c2 = cc + (q & 1);
                    if (c2 < YY) {
                        float v = acc[i][j][q] + biasg[c2] + g_xlast[(size_t)r2 * YY + c2];
                        dout[((size_t)r2 * DS + dstep) * YY + c2] = v;
                        g_xlast[(size_t)r2 * YY + c2] = v;
                        g_xlastf[(size_t)r2 * KPAD + c2] = __float2half_rn(v);
                    }
                }
            }
        }
    } else {  // M_GATE0 / M_GATE1: acc -> smem -> fused gate math
#pragma unroll
        for (int i = 0; i < IC; i++) {
            int rl = warpM * (BM / 2) + i * 16 + lane4;
#pragma unroll
            for (int j = 0; j < 6; j++) {
                int cl = warpN * 48 + j * 8 + lq * 2;
                *(float2*)&sm[rl * SEPIL + cl]       = make_float2(acc[i][j][0], acc[i][j][1]);
                *(float2*)&sm[(rl + 8) * SEPIL + cl] = make_float2(acc[i][j][2], acc[i][j][3]);
            }
        }
        __syncthreads();
        const int jbase = n0 / 3;   // 64 * blockIdx.x
        for (int idx = tid; idx < BM * 64; idx += NTH) {
            int bl = idx >> 6, jj = idx & 63;
            int b = m0 + bl;
            int cg = n0 + 3 * jj;
            float ar = sm[bl * SEPIL + 3 * jj + 0];
            float az = sm[bl * SEPIL + 3 * jj + 1];
            float an = sm[bl * SEPIL + 3 * jj + 2];
            float xr, xz, xn, gr, gz, gn, hp;
            if (MODE == M_GATE0) {
                const float* xg = gh + (size_t)b * GG;
                xr = xg[cg]; xz = xg[cg + 1]; xn = xg[cg + 2];
                gr = ar + bhh[cg]; gz = az + bhh[cg + 1]; gn = an + bhh[cg + 2];
                hp = hsrc[(size_t)b * HH + jbase + jj];
            } else {
                xr = ar + biasg[cg]; xz = az + biasg[cg + 1]; xn = an + biasg[cg + 2];
                if (ZG) {
                    gr = bhh[cg]; gz = bhh[cg + 1]; gn = bhh[cg + 2]; hp = 0.f;
                } else {
                    const float* g = gh + (size_t)b * GG;
                    gr = g[cg]; gz = g[cg + 1]; gn = g[cg + 2];
                    hp = hsrc[(size_t)b * HH + jbase + jj];
                }
            }
            float r = sigm(xr + gr), z = sigm(xz + gz);
            float nn_ = tanhf_(xn + r * gn);
            float hv = (1.f - z) * nn_ + z * hp;
            hdst[(size_t)b * HH + jbase + jj] = hv;
            hdstf[(size_t)b * HH + jbase + jj] = __float2half_rn(hv);
        }
    }
}

// ---------------- kernels ----------------
#define SM128 (3 * (128 + 192) * 128)   // 122880
#define SM64  (3 * (64 + 192) * 128)    //  98304

__global__ void __launch_bounds__(NTH, 1) k_rec(int par, int slot) {
    if (blockIdx.z == 0)
        gcore<128, M_GATE0, 8, false, false>(g_h0f[par ^ 1], HH, g_Whh0h, HH,
            nullptr, g_xg0 + (size_t)slot * BATCH * GG, g_bhh0p,
            g_h0[par ^ 1], g_h0[par], g_h0f[par], nullptr, nullptr, 0);
    else
        gcore<128, M_STORE, 8, false, false>(g_h1f[par ^ 1], HH, g_Whh1h, HH,
            g_bhh1p, nullptr, nullptr, nullptr, nullptr, nullptr, g_gh1, nullptr, 0);
}

template<bool ZG>
__global__ void __launch_bounds__(NTH, 1) k_xg1(int par) {
    gcore<64, M_GATE1, 8, ZG, false>(g_h0f[par], HH, g_Wih1h, HH,
        g_bih1p, g_gh1, g_bhh1p,
        g_h1[par ^ 1], g_h1[par], g_h1f[par], nullptr, nullptr, 0);
}

__global__ void __launch_bounds__(NTH, 1) k_xg0_all() {
    gcore<128, M_XGALL, 3, false, false>(g_xpf, KPAD, g_Wih0h, KPAD,
        g_bih0p, nullptr, nullptr, nullptr, nullptr, nullptr, g_xg0, nullptr, 0);
}

__global__ void __launch_bounds__(NTH, 1) k_xg0_new(int slot) {
    gcore<64, M_STORE, 3, false, false>(g_xlastf, KPAD, g_Wih0h, KPAD,
        g_bih0p, nullptr, nullptr, nullptr, nullptr, nullptr,
        g_xg0 + (size_t)slot * BATCH * GG, nullptr, 0);
}

__global__ void __launch_bounds__(NTH, 1) k_out(float* __restrict__ dout, int dstep,
                                                const float* __restrict__ bout) {
    gcore<64, M_OUT, 8, false, true>(g_h1f[0], HH, g_Wouth, HH,
        bout, nullptr, nullptr, nullptr, nullptr, nullptr, nullptr, dout, dstep);
}

__global__ void k_gate0_init(int slot) {
    int idx = blockIdx.x * blockDim.x + threadIdx.x;
    if (idx >= BATCH * HH) return;
    int b = idx >> 9, j = idx & 511;
    const float* xg = g_xg0 + (size_t)slot * BATCH * GG + (size_t)b * GG;
    int c = 3 * j;
    float r = sigm(xg[c] + g_bhh0p[c]);
    float z = sigm(xg[c + 1] + g_bhh0p[c + 1]);
    float n = tanhf_(xg[c + 2] + r * g_bhh0p[c + 2]);
    float hv = (1.f - z) * n;
    g_h0[0][idx] = hv;
    g_h0f[0][idx] = __float2half_rn(hv);
}

__global__ void k_init(const float* __restrict__ x) {
    int idx = blockIdx.x * blockDim.x + threadIdx.x;
    if (idx < BATCH * TT * KPAD) {
        int row = idx / KPAD, k = idx % KPAD;
        g_xpf[idx] = (k < YY) ? __float2half_rn(x[(size_t)row * YY + k]) : __float2half_rn(0.f);
    }
    if (idx < BATCH * KPAD) {
        int b = idx / KPAD, k = idx % KPAD;
        if (k < YY) {
            float v = x[((size_t)b * TT + (TT - 1)) * YY + k];
            g_xlast[(size_t)b * YY + k] = v;
            g_xlastf[idx] = __float2half_rn(v);
        } else {
            g_xlastf[idx] = __float2half_rn(0.f);
        }
    }
}

__global__ void k_prep(const float* __restrict__ Wih0, const float* __restrict__ Whh0,
                       const float* __restrict__ bih0, const float* __restrict__ bhh0,
                       const float* __restrict__ Wih1, const float* __restrict__ Whh1,
                       const float* __restrict__ bih1, const float* __restrict__ bhh1,
                       const float* __restrict__ Wout) {
    int i = blockIdx.x * blockDim.x + threadIdx.x;
    if (i < GG * HH) {
        int c = i / HH, k = i % HH;
        int pr = (c % 3) * HH + c / 3;
        g_Whh0h[i] = __float2half_rn(Whh0[(size_t)pr * HH + k]);
        g_Wih1h[i] = __float2half_rn(Wih1[(size_t)pr * HH + k]);
        g_Whh1h[i] = __float2half_rn(Whh1[(size_t)pr * HH + k]);
    }
    if (i < GG * KPAD) {
        int c = i / KPAD, k = i % KPAD;
        int pr = (c % 3) * HH + c / 3;
        g_Wih0h[i] = (k < YY) ? __float2half_rn(Wih0[(size_t)pr * YY + k]) : __float2half_rn(0.f);
    }
    if (i < KPAD * HH) {
        int r = i / HH, k = i % HH;
        g_Wouth[i] = (r < YY) ? __float2half_rn(Wout[(size_t)r * HH + k]) : __float2half_rn(0.f);
    }
    if (i < GG) {
        int pr = (i % 3) * HH + i / 3;
        g_bih0p[i] = bih0[pr];
        g_bhh0p[i] = bhh0[pr];
        g_bih1p[i] = bih1[pr];
        g_bhh1p[i] = bhh1[pr];
    }
}

// ---------------- host ----------------
extern "C" void kernel_launch(void* const* d_in, const int* in_sizes, int n_in,
                              void* d_out, int out_size) {
    (void)in_sizes; (void)n_in; (void)out_size;
    const float* x    = (const float*)d_in[0];
    const float* Wih0 = (const float*)d_in[1];
    const float* Whh0 = (const float*)d_in[2];
    const float* bih0 = (const float*)d_in[3];
    const float* bhh0 = (const float*)d_in[4];
    const float* Wih1 = (const float*)d_in[5];
    const float* Whh1 = (const float*)d_in[6];
    const float* bih1 = (const float*)d_in[7];
    const float* bhh1 = (const float*)d_in[8];
    const float* Wout = (const float*)d_in[9];
    const float* bout = (const float*)d_in[10];
    float* dout = (float*)d_out;

    cudaFuncSetAttribute(k_rec,        cudaFuncAttributeMaxDynamicSharedMemorySize, SM128);
    cudaFuncSetAttribute(k_xg0_all,    cudaFuncAttributeMaxDynamicSharedMemorySize, SM128);
    cudaFuncSetAttribute(k_xg1<true>,  cudaFuncAttributeMaxDynamicSharedMemorySize, SM64);
    cudaFuncSetAttribute(k_xg1<false>, cudaFuncAttributeMaxDynamicSharedMemorySize, SM64);
    cudaFuncSetAttribute(k_xg0_new,    cudaFuncAttributeMaxDynamicSharedMemorySize, SM64);
    cudaFuncSetAttribute(k_out,        cudaFuncAttributeMaxDynamicSharedMemorySize, SM64);

    k_prep<<<(GG * HH + 255) / 256, 256>>>(Wih0, Whh0, bih0, bhh0,
                                           Wih1, Whh1, bih1, bhh1, Wout);
    k_init<<<(BATCH * TT * KPAD + 255) / 256, 256>>>(x);
    k_xg0_all<<<dim3(GG / 192, BATCH * TT / 128), NTH, SM128>>>();

    for (int d = 0; d < DS; d++) {
        k_gate0_init<<<(BATCH * HH + 255) / 256, 256>>>(d % TT);
        k_xg1<true><<<dim3(GG / 192, BATCH / 64), NTH, SM64>>>(0);
        for (int t = 1; t < TT; t++) {
            k_rec<<<dim3(GG / 192, BATCH / 128, 2), NTH, SM128>>>(t & 1, (d + t) % TT);
            k_xg1<false><<<dim3(GG / 192, BATCH / 64), NTH, SM64>>>(t & 1);
        }
        k_out<<<dim3(1, BATCH / 64), NTH, SM64>>>(dout, d, bout);
        if (d + 1 < DS) k_xg0_new<<<dim3(GG / 192, BATCH / 64), NTH, SM64>>>(d % TT);
    }
}